// round 2
// baseline (speedup 1.0000x reference)
#include <cuda_runtime.h>
#include <cuda_bf16.h>
#include <math.h>

#define BB 4
#define HH 512
#define WW 512
#define NUM_INST 32
#define EPS 1e-5f

// Ping-pong activation buffers: max activation = 4*16*512*512 floats = 64MB
__device__ float g_bufA[BB * 16 * HH * WW];
__device__ float g_bufB[BB * 16 * HH * WW];
__device__ float g_means[NUM_INST * 3];

// ---------------------------------------------------------------------------
// conv0: reflect-pad 3, 7x7, Cin=3 -> Cout=16, stride 1
// One thread per output pixel, computes all 16 output channels.
// ---------------------------------------------------------------------------
__global__ void conv0_k(const float* __restrict__ x, const float* __restrict__ w,
                        const float* __restrict__ bias, float* __restrict__ y) {
    int idx = blockIdx.x * blockDim.x + threadIdx.x;
    if (idx >= BB * HH * WW) return;
    int ww = idx % WW;
    int hh = (idx / WW) % HH;
    int n = idx / (HH * WW);

    float acc[16];
#pragma unroll
    for (int co = 0; co < 16; co++) acc[co] = bias[co];

#pragma unroll
    for (int ci = 0; ci < 3; ci++) {
        const float* xp = x + (size_t)(n * 3 + ci) * HH * WW;
        for (int kh = 0; kh < 7; kh++) {
            int ih = hh + kh - 3;
            ih = ih < 0 ? -ih : (ih >= HH ? 2 * HH - 2 - ih : ih);
            const float* xrow = xp + ih * WW;
            for (int kw = 0; kw < 7; kw++) {
                int iw = ww + kw - 3;
                iw = iw < 0 ? -iw : (iw >= WW ? 2 * WW - 2 - iw : iw);
                float xv = xrow[iw];
                const float* wp = w + (ci * 7 + kh) * 7 + kw;
#pragma unroll
                for (int co = 0; co < 16; co++)
                    acc[co] = fmaf(xv, wp[co * 3 * 49], acc[co]);
            }
        }
    }
    size_t base = (size_t)n * 16 * HH * WW + (size_t)hh * WW + ww;
#pragma unroll
    for (int co = 0; co < 16; co++) y[base + (size_t)co * HH * WW] = acc[co];
}

// ---------------------------------------------------------------------------
// 3x3 stride-2 conv, zero pad 1. 8 output channels per thread.
// grid.x covers spatial, grid.y = n * (COUT/8) + cog
// ---------------------------------------------------------------------------
template <int CIN, int COUT>
__global__ void conv_s2_k(const float* __restrict__ x, const float* __restrict__ w,
                          const float* __restrict__ bias, float* __restrict__ y,
                          int Hin, int Win) {
    int Hout = Hin >> 1, Wout = Win >> 1;
    int sp = blockIdx.x * blockDim.x + threadIdx.x;
    if (sp >= Hout * Wout) return;
    int ow = sp % Wout, oh = sp / Wout;
    int cog = blockIdx.y % (COUT / 8);
    int n = blockIdx.y / (COUT / 8);

    float acc[8];
#pragma unroll
    for (int u = 0; u < 8; u++) acc[u] = bias[cog * 8 + u];

    for (int ci = 0; ci < CIN; ci++) {
        const float* xp = x + (size_t)(n * CIN + ci) * Hin * Win;
        const float* wp = w + (size_t)(cog * 8 * CIN + ci) * 9;
#pragma unroll
        for (int kh = 0; kh < 3; kh++) {
            int ih = oh * 2 + kh - 1;
            if ((unsigned)ih >= (unsigned)Hin) continue;
#pragma unroll
            for (int kw = 0; kw < 3; kw++) {
                int iw = ow * 2 + kw - 1;
                if ((unsigned)iw >= (unsigned)Win) continue;
                float xv = xp[ih * Win + iw];
#pragma unroll
                for (int u = 0; u < 8; u++)
                    acc[u] = fmaf(xv, wp[u * CIN * 9 + kh * 3 + kw], acc[u]);
            }
        }
    }
    size_t base = ((size_t)(n * COUT + cog * 8) * Hout + oh) * Wout + ow;
#pragma unroll
    for (int u = 0; u < 8; u++) y[base + (size_t)u * Hout * Wout] = acc[u];
}

// ---------------------------------------------------------------------------
// ConvTranspose2d k=3 s=2 p=1 output_padding=1. Weight layout (CIN, COUT, 3, 3).
// y[n,co,oh,ow] = sum_{kh,kw : (oh+1-kh)%2==0, ih in range} sum_ci x[n,ci,ih,iw]*w[ci,co,kh,kw]
// 8 output channels per thread.
// ---------------------------------------------------------------------------
template <int CIN, int COUT>
__global__ void deconv_k(const float* __restrict__ x, const float* __restrict__ w,
                         const float* __restrict__ bias, float* __restrict__ y,
                         int Hin, int Win) {
    int Hout = Hin * 2, Wout = Win * 2;
    int sp = blockIdx.x * blockDim.x + threadIdx.x;
    if (sp >= Hout * Wout) return;
    int ow = sp % Wout, oh = sp / Wout;
    int cog = blockIdx.y % (COUT / 8);
    int n = blockIdx.y / (COUT / 8);
    int co0 = cog * 8;

    float acc[8];
#pragma unroll
    for (int u = 0; u < 8; u++) acc[u] = bias[co0 + u];

#pragma unroll
    for (int kh = 0; kh < 3; kh++) {
        int t = oh + 1 - kh;
        if (t & 1) continue;
        int ih = t >> 1;
        if ((unsigned)ih >= (unsigned)Hin) continue;
#pragma unroll
        for (int kw = 0; kw < 3; kw++) {
            int s2 = ow + 1 - kw;
            if (s2 & 1) continue;
            int iw = s2 >> 1;
            if ((unsigned)iw >= (unsigned)Win) continue;
            const float* xp = x + ((size_t)n * CIN * Hin + ih) * Win + iw;
            const float* wp = w + (size_t)co0 * 9 + kh * 3 + kw;
            for (int ci = 0; ci < CIN; ci++) {
                float xv = xp[(size_t)ci * Hin * Win];
#pragma unroll
                for (int u = 0; u < 8; u++)
                    acc[u] = fmaf(xv, wp[(size_t)(ci * COUT + u) * 9], acc[u]);
            }
        }
    }
    size_t base = ((size_t)(n * COUT + co0) * Hout + oh) * Wout + ow;
#pragma unroll
    for (int u = 0; u < 8; u++) y[base + (size_t)u * Hout * Wout] = acc[u];
}

// ---------------------------------------------------------------------------
// Fused InstanceNorm (biased var) + ReLU, in place. One block per (n,c) plane.
// ---------------------------------------------------------------------------
__global__ void inorm_relu_k(float* __restrict__ x, int HWp) {
    float* p = x + (size_t)blockIdx.x * HWp;
    int tid = threadIdx.x;
    float s = 0.f, s2 = 0.f;
    for (int i = tid; i < HWp; i += blockDim.x) {
        float v = p[i];
        s += v;
        s2 += v * v;
    }
    __shared__ float shs[512];
    __shared__ float shq[512];
    shs[tid] = s;
    shq[tid] = s2;
    __syncthreads();
    for (int o = 256; o > 0; o >>= 1) {
        if (tid < o) {
            shs[tid] += shs[tid + o];
            shq[tid] += shq[tid + o];
        }
        __syncthreads();
    }
    float inv = 1.0f / (float)HWp;
    float mean = shs[0] * inv;
    float var = shq[0] * inv - mean * mean;
    float r = rsqrtf(var + EPS);
    for (int i = tid; i < HWp; i += blockDim.x) {
        float v = (p[i] - mean) * r;
        p[i] = fmaxf(v, 0.f);
    }
}

// ---------------------------------------------------------------------------
// conv9: reflect-pad 3, 7x7, 16 -> 3, tanh
// ---------------------------------------------------------------------------
__global__ void conv9_k(const float* __restrict__ x, const float* __restrict__ w,
                        const float* __restrict__ bias, float* __restrict__ y) {
    int idx = blockIdx.x * blockDim.x + threadIdx.x;
    if (idx >= BB * HH * WW) return;
    int ww = idx % WW;
    int hh = (idx / WW) % HH;
    int n = idx / (HH * WW);

    float a0 = bias[0], a1 = bias[1], a2 = bias[2];
    for (int ci = 0; ci < 16; ci++) {
        const float* xp = x + (size_t)(n * 16 + ci) * HH * WW;
        const float* wp = w + ci * 49;
        for (int kh = 0; kh < 7; kh++) {
            int ih = hh + kh - 3;
            ih = ih < 0 ? -ih : (ih >= HH ? 2 * HH - 2 - ih : ih);
            const float* xrow = xp + ih * WW;
            for (int kw = 0; kw < 7; kw++) {
                int iw = ww + kw - 3;
                iw = iw < 0 ? -iw : (iw >= WW ? 2 * WW - 2 - iw : iw);
                float xv = xrow[iw];
                int wi = kh * 7 + kw;
                a0 = fmaf(xv, wp[wi], a0);
                a1 = fmaf(xv, wp[16 * 49 + wi], a1);
                a2 = fmaf(xv, wp[32 * 49 + wi], a2);
            }
        }
    }
    size_t base = (size_t)n * 3 * HH * WW + (size_t)hh * WW + ww;
    y[base] = tanhf(a0);
    y[base + (size_t)HH * WW] = tanhf(a1);
    y[base + 2 * (size_t)HH * WW] = tanhf(a2);
}

// ---------------------------------------------------------------------------
// Segment mean: one block per instance label, deterministic tree reduction.
// feats: [B,3,H,W], inst: [B,1,H,W]
// ---------------------------------------------------------------------------
__global__ void segreduce_k(const float* __restrict__ feats, const int* __restrict__ inst) {
    int s = blockIdx.x;
    int tid = threadIdx.x;
    const int HWp = HH * WW;
    float c0 = 0.f, c1 = 0.f, c2 = 0.f, cnt = 0.f;
    for (int p = tid; p < BB * HWp; p += blockDim.x) {
        if (inst[p] == s) {
            int n = p / HWp;
            int hw = p - n * HWp;
            const float* f = feats + (size_t)n * 3 * HWp + hw;
            c0 += f[0];
            c1 += f[HWp];
            c2 += f[2 * HWp];
            cnt += 1.f;
        }
    }
    __shared__ float sh0[256], sh1[256], sh2[256], shc[256];
    sh0[tid] = c0; sh1[tid] = c1; sh2[tid] = c2; shc[tid] = cnt;
    __syncthreads();
    for (int o = 128; o > 0; o >>= 1) {
        if (tid < o) {
            sh0[tid] += sh0[tid + o];
            sh1[tid] += sh1[tid + o];
            sh2[tid] += sh2[tid + o];
            shc[tid] += shc[tid + o];
        }
        __syncthreads();
    }
    if (tid == 0) {
        float d = fmaxf(shc[0], 1.0f);
        g_means[s * 3 + 0] = sh0[0] / d;
        g_means[s * 3 + 1] = sh1[0] / d;
        g_means[s * 3 + 2] = sh2[0] / d;
    }
}

__global__ void gather_k(const int* __restrict__ inst, float* __restrict__ out) {
    int idx = blockIdx.x * blockDim.x + threadIdx.x;
    const int HWp = HH * WW;
    if (idx >= BB * 3 * HWp) return;
    int hw = idx % HWp;
    int c = (idx / HWp) % 3;
    int n = idx / (3 * HWp);
    out[idx] = g_means[inst[n * HWp + hw] * 3 + c];
}

// ---------------------------------------------------------------------------
extern "C" void kernel_launch(void* const* d_in, const int* in_sizes, int n_in,
                              void* d_out, int out_size) {
    const float* input = (const float*)d_in[0];
    const int* inst = (const int*)d_in[1];
    const float* w0 = (const float*)d_in[2];  const float* b0 = (const float*)d_in[3];
    const float* w1 = (const float*)d_in[4];  const float* b1 = (const float*)d_in[5];
    const float* w2 = (const float*)d_in[6];  const float* b2 = (const float*)d_in[7];
    const float* w3 = (const float*)d_in[8];  const float* b3 = (const float*)d_in[9];
    const float* w4 = (const float*)d_in[10]; const float* b4 = (const float*)d_in[11];
    const float* w5 = (const float*)d_in[12]; const float* b5 = (const float*)d_in[13];
    const float* w6 = (const float*)d_in[14]; const float* b6 = (const float*)d_in[15];
    const float* w7 = (const float*)d_in[16]; const float* b7 = (const float*)d_in[17];
    const float* w8 = (const float*)d_in[18]; const float* b8 = (const float*)d_in[19];
    const float* w9 = (const float*)d_in[20]; const float* b9 = (const float*)d_in[21];
    float* out = (float*)d_out;

    float* bufA;
    float* bufB;
    cudaGetSymbolAddress((void**)&bufA, g_bufA);
    cudaGetSymbolAddress((void**)&bufB, g_bufB);

    const int HWp = HH * WW;

    // conv0 + IN + ReLU : [4,3,512,512] -> [4,16,512,512]
    conv0_k<<<(BB * HWp + 255) / 256, 256>>>(input, w0, b0, bufA);
    inorm_relu_k<<<BB * 16, 512>>>(bufA, HWp);

    // conv1..conv4 (3x3 s2)
    conv_s2_k<16, 32><<<dim3(256, BB * 4), 256>>>(bufA, w1, b1, bufB, 512, 512);
    inorm_relu_k<<<BB * 32, 512>>>(bufB, 256 * 256);

    conv_s2_k<32, 64><<<dim3(64, BB * 8), 256>>>(bufB, w2, b2, bufA, 256, 256);
    inorm_relu_k<<<BB * 64, 512>>>(bufA, 128 * 128);

    conv_s2_k<64, 128><<<dim3(16, BB * 16), 256>>>(bufA, w3, b3, bufB, 128, 128);
    inorm_relu_k<<<BB * 128, 512>>>(bufB, 64 * 64);

    conv_s2_k<128, 256><<<dim3(4, BB * 32), 256>>>(bufB, w4, b4, bufA, 64, 64);
    inorm_relu_k<<<BB * 256, 512>>>(bufA, 32 * 32);

    // deconv5..deconv8
    deconv_k<256, 128><<<dim3(16, BB * 16), 256>>>(bufA, w5, b5, bufB, 32, 32);
    inorm_relu_k<<<BB * 128, 512>>>(bufB, 64 * 64);

    deconv_k<128, 64><<<dim3(64, BB * 8), 256>>>(bufB, w6, b6, bufA, 64, 64);
    inorm_relu_k<<<BB * 64, 512>>>(bufA, 128 * 128);

    deconv_k<64, 32><<<dim3(256, BB * 4), 256>>>(bufA, w7, b7, bufB, 128, 128);
    inorm_relu_k<<<BB * 32, 512>>>(bufB, 256 * 256);

    deconv_k<32, 16><<<dim3(1024, BB * 2), 256>>>(bufB, w8, b8, bufA, 256, 256);
    inorm_relu_k<<<BB * 16, 512>>>(bufA, HWp);

    // conv9 + tanh : [4,16,512,512] -> [4,3,512,512]
    conv9_k<<<(BB * HWp + 255) / 256, 256>>>(bufA, w9, b9, bufB);

    // segment mean + gather
    segreduce_k<<<NUM_INST, 256>>>(bufB, inst);
    gather_k<<<(BB * 3 * HWp + 255) / 256, 256>>>(inst, out);
}

// round 5
// speedup vs baseline: 2.6185x; 2.6185x over previous
#include <cuda_runtime.h>
#include <math.h>

#define BB 4
#define HH 512
#define WW 512
#define NUM_INST 32
#define EPS 1e-5f

// Ping-pong activation buffers (max 4*16*512*512 floats = 64MB each)
__device__ float g_bufA[BB * 16 * HH * WW];
__device__ float g_bufB[BB * 16 * HH * WW];
__device__ float g_stats[BB * 256 * 2];   // (mean, rstd) per (n,channel) plane
__device__ float g_means[NUM_INST * 3];
__device__ float g_part[NUM_INST * 8 * 4];

__device__ __forceinline__ int refl(int i, int n) {
    return i < 0 ? -i : (i >= n ? 2 * n - 2 - i : i);
}

// ---------------------------------------------------------------------------
// Per-plane stats: mean + rstd (biased var), one block per (n,c) plane.
// ---------------------------------------------------------------------------
__global__ void stats_k(const float* __restrict__ x, int HWp) {
    const float4* p4 = (const float4*)(x + (size_t)blockIdx.x * HWp);
    int n4 = HWp >> 2;
    float s = 0.f, q = 0.f;
    for (int i = threadIdx.x; i < n4; i += 256) {
        float4 v = p4[i];
        s += v.x + v.y + v.z + v.w;
        q += v.x * v.x + v.y * v.y + v.z * v.z + v.w * v.w;
    }
    __shared__ float ss[256], sq[256];
    ss[threadIdx.x] = s; sq[threadIdx.x] = q;
    __syncthreads();
    for (int o = 128; o > 0; o >>= 1) {
        if (threadIdx.x < o) { ss[threadIdx.x] += ss[threadIdx.x + o]; sq[threadIdx.x] += sq[threadIdx.x + o]; }
        __syncthreads();
    }
    if (threadIdx.x == 0) {
        float inv = 1.f / (float)HWp;
        float m = ss[0] * inv;
        float var = sq[0] * inv - m * m;
        g_stats[blockIdx.x * 2] = m;
        g_stats[blockIdx.x * 2 + 1] = rsqrtf(var + EPS);
    }
}

// ---------------------------------------------------------------------------
// 3x3 stride-2 conv, zero pad 1, with fused InstanceNorm+ReLU applied to the
// INPUT (stats from previous layer in g_stats). Thread = TSxTS outputs x COPT
// output channels. Weights staged in smem.
// ---------------------------------------------------------------------------
template <int CIN, int COUT, int COPT, int TS, int HIN, int WIN, bool NORM>
__global__ void __launch_bounds__(256) conv_s2_t(const float* __restrict__ x,
                                                 const float* __restrict__ w,
                                                 const float* __restrict__ bias,
                                                 float* __restrict__ y) {
    constexpr int HOUT = HIN / 2, WOUT = WIN / 2;
    constexpr int TW = WOUT / TS;
    constexpr int CHUNK = (CIN < 64) ? CIN : 64;
    constexpr int NX = 2 * TS + 1;
    __shared__ float wsm[CHUNK * 9 * COPT];

    int t = blockIdx.x * 256 + threadIdx.x;
    int cog = blockIdx.y % (COUT / COPT);
    int n = blockIdx.y / (COUT / COPT);
    int oh0 = (t / TW) * TS, ow0 = (t % TW) * TS;

    int iwv[NX]; bool cvl[NX];
#pragma unroll
    for (int c = 0; c < NX; c++) {
        int iw = ow0 * 2 - 1 + c;
        iwv[c] = iw;
        cvl[c] = (unsigned)iw < (unsigned)WIN;
    }

    float acc[TS * TS * COPT];
#pragma unroll
    for (int i = 0; i < TS * TS * COPT; i++) acc[i] = 0.f;

#pragma unroll 1
    for (int c0 = 0; c0 < CIN; c0 += CHUNK) {
        __syncthreads();
        for (int i = threadIdx.x; i < CHUNK * 9 * COPT; i += 256) {
            int ci_l = i / (9 * COPT);
            int rem = i - ci_l * (9 * COPT);
            int tap = rem / COPT;
            int u = rem - tap * COPT;
            wsm[i] = w[((size_t)(cog * COPT + u) * CIN + c0 + ci_l) * 9 + tap];
        }
        __syncthreads();
#pragma unroll 1
        for (int ci_l = 0; ci_l < CHUNK; ci_l++) {
            int ci = c0 + ci_l;
            const float* xp = x + (size_t)(n * CIN + ci) * HIN * WIN;
            float mn = 0.f, rs = 1.f;
            if (NORM) {
                mn = g_stats[(n * CIN + ci) * 2];
                rs = g_stats[(n * CIN + ci) * 2 + 1];
            }
#pragma unroll 1
            for (int r = 0; r < NX; r++) {
                int ih = oh0 * 2 - 1 + r;
                bool rv = (unsigned)ih < (unsigned)HIN;
                const float* xr = xp + (size_t)ih * WIN;
                float xv[NX];
#pragma unroll
                for (int c = 0; c < NX; c++) {
                    bool v = rv && cvl[c];
                    float raw = v ? xr[iwv[c]] : 0.f;
                    xv[c] = (NORM && v) ? fmaxf((raw - mn) * rs, 0.f) : raw;
                }
#pragma unroll
                for (int orow = 0; orow < TS; orow++) {
                    int kh = r - 2 * orow;
                    if (kh >= 0 && kh < 3) {
                        const float* wp = wsm + (ci_l * 9 + kh * 3) * COPT;
#pragma unroll
                        for (int kw = 0; kw < 3; kw++) {
#pragma unroll
                            for (int u = 0; u < COPT; u++) {
                                float wvv = wp[kw * COPT + u];
#pragma unroll
                                for (int oc = 0; oc < TS; oc++)
                                    acc[(orow * TS + oc) * COPT + u] =
                                        fmaf(xv[2 * oc + kw], wvv, acc[(orow * TS + oc) * COPT + u]);
                            }
                        }
                    }
                }
            }
        }
    }
    size_t obase = (size_t)(n * COUT + cog * COPT) * HOUT * WOUT + (size_t)oh0 * WOUT + ow0;
#pragma unroll
    for (int u = 0; u < COPT; u++) {
        float bv = bias[cog * COPT + u];
#pragma unroll
        for (int orow = 0; orow < TS; orow++) {
            float* yp = y + obase + (size_t)u * HOUT * WOUT + (size_t)orow * WOUT;
            if (TS == 4) {
                float4 v;
                v.x = acc[(orow * TS + 0) * COPT + u] + bv;
                v.y = acc[(orow * TS + 1) * COPT + u] + bv;
                v.z = acc[(orow * TS + 2) * COPT + u] + bv;
                v.w = acc[(orow * TS + 3) * COPT + u] + bv;
                *reinterpret_cast<float4*>(yp) = v;
            } else {
#pragma unroll
                for (int oc = 0; oc < TS; oc++) yp[oc] = acc[(orow * TS + oc) * COPT + u] + bv;
            }
        }
    }
}

// ---------------------------------------------------------------------------
// ConvTranspose2d k=3 s=2 p=1 op=1, fused norm+relu on input.
// Thread = TSxTS outputs (TS even) x COPT channels. Input footprint is
// (TS/2+1)^2. Weight layout (CIN, COUT, 3, 3).
// ---------------------------------------------------------------------------
template <int CIN, int COUT, int COPT, int TS, int HIN, int WIN, bool NORM>
__global__ void __launch_bounds__(256) deconv_t(const float* __restrict__ x,
                                                const float* __restrict__ w,
                                                const float* __restrict__ bias,
                                                float* __restrict__ y) {
    constexpr int HOUT = HIN * 2, WOUT = WIN * 2;
    constexpr int TW = WOUT / TS;
    constexpr int SUB = TS / 2;
    constexpr int CHUNK = (CIN < 64) ? CIN : 64;
    __shared__ float wsm[CHUNK * 9 * COPT];

    int t = blockIdx.x * 256 + threadIdx.x;
    int cog = blockIdx.y % (COUT / COPT);
    int n = blockIdx.y / (COUT / COPT);
    int oh0 = (t / TW) * TS, ow0 = (t % TW) * TS;
    int i0 = oh0 >> 1, j0 = ow0 >> 1;

    float acc[TS * TS * COPT];
#pragma unroll
    for (int i = 0; i < TS * TS * COPT; i++) acc[i] = 0.f;

#pragma unroll 1
    for (int c0 = 0; c0 < CIN; c0 += CHUNK) {
        __syncthreads();
        for (int i = threadIdx.x; i < CHUNK * 9 * COPT; i += 256) {
            int ci_l = i / (9 * COPT);
            int rem = i - ci_l * (9 * COPT);
            int tap = rem / COPT;
            int u = rem - tap * COPT;
            wsm[i] = w[((size_t)(c0 + ci_l) * COUT + cog * COPT + u) * 9 + tap];
        }
        __syncthreads();
#pragma unroll 1
        for (int ci_l = 0; ci_l < CHUNK; ci_l++) {
            int ci = c0 + ci_l;
            const float* xp = x + (size_t)(n * CIN + ci) * HIN * WIN;
            float mn = 0.f, rs = 1.f;
            if (NORM) {
                mn = g_stats[(n * CIN + ci) * 2];
                rs = g_stats[(n * CIN + ci) * 2 + 1];
            }
            float xr[(SUB + 1) * (SUB + 1)];
#pragma unroll
            for (int r = 0; r <= SUB; r++) {
                bool rv = (i0 + r) < HIN;
                const float* xpr = xp + (size_t)(i0 + r) * WIN;
#pragma unroll
                for (int c = 0; c <= SUB; c++) {
                    bool v = rv && (j0 + c) < WIN;
                    float raw = v ? xpr[j0 + c] : 0.f;
                    xr[r * (SUB + 1) + c] = (NORM && v) ? fmaxf((raw - mn) * rs, 0.f) : raw;
                }
            }
#pragma unroll
            for (int kh = 0; kh < 3; kh++) {
                int orl = (kh == 1) ? 0 : 1;
                int xro = (kh == 0) ? 1 : 0;
#pragma unroll
                for (int kw = 0; kw < 3; kw++) {
                    int ocl = (kw == 1) ? 0 : 1;
                    int xco = (kw == 0) ? 1 : 0;
                    const float* wp = wsm + (ci_l * 9 + kh * 3 + kw) * COPT;
#pragma unroll
                    for (int u = 0; u < COPT; u++) {
                        float wvv = wp[u];
#pragma unroll
                        for (int a = 0; a < SUB; a++)
#pragma unroll
                            for (int b = 0; b < SUB; b++)
                                acc[((2 * a + orl) * TS + (2 * b + ocl)) * COPT + u] =
                                    fmaf(xr[(a + xro) * (SUB + 1) + (b + xco)], wvv,
                                         acc[((2 * a + orl) * TS + (2 * b + ocl)) * COPT + u]);
                    }
                }
            }
        }
    }
    size_t obase = (size_t)(n * COUT + cog * COPT) * HOUT * WOUT + (size_t)oh0 * WOUT + ow0;
#pragma unroll
    for (int u = 0; u < COPT; u++) {
        float bv = bias[cog * COPT + u];
#pragma unroll
        for (int orow = 0; orow < TS; orow++) {
            float* yp = y + obase + (size_t)u * HOUT * WOUT + (size_t)orow * WOUT;
            float4 v;
            v.x = acc[(orow * TS + 0) * COPT + u] + bv;
            v.y = acc[(orow * TS + 1) * COPT + u] + bv;
            v.z = acc[(orow * TS + 2) * COPT + u] + bv;
            v.w = acc[(orow * TS + 3) * COPT + u] + bv;
            *reinterpret_cast<float4*>(yp) = v;
        }
    }
}

// ---------------------------------------------------------------------------
// conv0: reflect-pad 3, 7x7, 3->16. Thread = 1 row x 8 cols, all 16 co.
// ---------------------------------------------------------------------------
__global__ void __launch_bounds__(256) conv7_first(const float* __restrict__ x,
                                                   const float* __restrict__ w,
                                                   const float* __restrict__ bias,
                                                   float* __restrict__ y) {
    __shared__ float wsm[3 * 49 * 16];
    for (int i = threadIdx.x; i < 3 * 49 * 16; i += 256) {
        int ci = i / (49 * 16);
        int rem = i - ci * (49 * 16);
        int tap = rem / 16;
        int co = rem - tap * 16;
        wsm[i] = w[(co * 3 + ci) * 49 + tap];
    }
    __syncthreads();

    int t = blockIdx.x * 256 + threadIdx.x;
    int n = blockIdx.y;
    int oh = t >> 6;
    int ow0 = (t & 63) * 8;

    int iwI[14];
#pragma unroll
    for (int c = 0; c < 14; c++) iwI[c] = refl(ow0 - 3 + c, WW);

    float acc[8 * 16];
#pragma unroll
    for (int i = 0; i < 8 * 16; i++) acc[i] = 0.f;

#pragma unroll 1
    for (int ci = 0; ci < 3; ci++) {
        const float* xp = x + (size_t)(n * 3 + ci) * HH * WW;
#pragma unroll 1
        for (int kh = 0; kh < 7; kh++) {
            const float* xr = xp + (size_t)refl(oh + kh - 3, HH) * WW;
            float xv[14];
#pragma unroll
            for (int c = 0; c < 14; c++) xv[c] = xr[iwI[c]];
            const float* wb = wsm + (ci * 49 + kh * 7) * 16;
#pragma unroll
            for (int kw = 0; kw < 7; kw++) {
#pragma unroll
                for (int co = 0; co < 16; co++) {
                    float wvv = wb[kw * 16 + co];
#pragma unroll
                    for (int sc = 0; sc < 8; sc++)
                        acc[sc * 16 + co] = fmaf(xv[sc + kw], wvv, acc[sc * 16 + co]);
                }
            }
        }
    }
#pragma unroll
    for (int co = 0; co < 16; co++) {
        float bv = bias[co];
        float* yp = y + (size_t)(n * 16 + co) * HH * WW + (size_t)oh * WW + ow0;
        float4 v0, v1;
        v0.x = acc[0 * 16 + co] + bv; v0.y = acc[1 * 16 + co] + bv;
        v0.z = acc[2 * 16 + co] + bv; v0.w = acc[3 * 16 + co] + bv;
        v1.x = acc[4 * 16 + co] + bv; v1.y = acc[5 * 16 + co] + bv;
        v1.z = acc[6 * 16 + co] + bv; v1.w = acc[7 * 16 + co] + bv;
        ((float4*)yp)[0] = v0;
        ((float4*)yp)[1] = v1;
    }
}

// ---------------------------------------------------------------------------
// conv9: reflect-pad 3, 7x7, 16->3, norm+relu on input, tanh on output.
// ---------------------------------------------------------------------------
__global__ void __launch_bounds__(256) conv7_last(const float* __restrict__ x,
                                                  const float* __restrict__ w,
                                                  const float* __restrict__ bias,
                                                  float* __restrict__ y) {
    __shared__ float wsm[16 * 49 * 3];
    for (int i = threadIdx.x; i < 16 * 49 * 3; i += 256) {
        int ci = i / (49 * 3);
        int rem = i - ci * (49 * 3);
        int tap = rem / 3;
        int co = rem - tap * 3;
        wsm[i] = w[(co * 16 + ci) * 49 + tap];
    }
    __syncthreads();

    int t = blockIdx.x * 256 + threadIdx.x;
    int n = blockIdx.y;
    int oh = t >> 6;
    int ow0 = (t & 63) * 8;

    int iwI[14];
#pragma unroll
    for (int c = 0; c < 14; c++) iwI[c] = refl(ow0 - 3 + c, WW);

    float acc[8 * 3];
#pragma unroll
    for (int i = 0; i < 8 * 3; i++) acc[i] = 0.f;

#pragma unroll 1
    for (int ci = 0; ci < 16; ci++) {
        const float* xp = x + (size_t)(n * 16 + ci) * HH * WW;
        float mn = g_stats[(n * 16 + ci) * 2];
        float rs = g_stats[(n * 16 + ci) * 2 + 1];
#pragma unroll 1
        for (int kh = 0; kh < 7; kh++) {
            const float* xr = xp + (size_t)refl(oh + kh - 3, HH) * WW;
            float xv[14];
#pragma unroll
            for (int c = 0; c < 14; c++) xv[c] = fmaxf((xr[iwI[c]] - mn) * rs, 0.f);
            const float* wb = wsm + (ci * 49 + kh * 7) * 3;
#pragma unroll
            for (int kw = 0; kw < 7; kw++) {
#pragma unroll
                for (int co = 0; co < 3; co++) {
                    float wvv = wb[kw * 3 + co];
#pragma unroll
                    for (int sc = 0; sc < 8; sc++)
                        acc[sc * 3 + co] = fmaf(xv[sc + kw], wvv, acc[sc * 3 + co]);
                }
            }
        }
    }
#pragma unroll
    for (int co = 0; co < 3; co++) {
        float bv = bias[co];
        float* yp = y + (size_t)(n * 3 + co) * HH * WW + (size_t)oh * WW + ow0;
        float4 v0, v1;
        v0.x = tanhf(acc[0 * 3 + co] + bv); v0.y = tanhf(acc[1 * 3 + co] + bv);
        v0.z = tanhf(acc[2 * 3 + co] + bv); v0.w = tanhf(acc[3 * 3 + co] + bv);
        v1.x = tanhf(acc[4 * 3 + co] + bv); v1.y = tanhf(acc[5 * 3 + co] + bv);
        v1.z = tanhf(acc[6 * 3 + co] + bv); v1.w = tanhf(acc[7 * 3 + co] + bv);
        ((float4*)yp)[0] = v0;
        ((float4*)yp)[1] = v1;
    }
}

// ---------------------------------------------------------------------------
// Segment mean: (label, slice) partials, deterministic, then combine.
// ---------------------------------------------------------------------------
__global__ void segpart_k(const float* __restrict__ feats, const int* __restrict__ inst) {
    int lab = blockIdx.x, slice = blockIdx.y;
    const int HWp = HH * WW;
    const int per = BB * HWp / 8;
    int start = slice * per;
    float c0 = 0.f, c1 = 0.f, c2 = 0.f, cnt = 0.f;
    for (int p = start + threadIdx.x; p < start + per; p += 256) {
        if (inst[p] == lab) {
            int n = p / HWp;
            int hw = p - n * HWp;
            const float* f = feats + (size_t)n * 3 * HWp + hw;
            c0 += f[0];
            c1 += f[HWp];
            c2 += f[2 * HWp];
            cnt += 1.f;
        }
    }
    __shared__ float s0[256], s1[256], s2[256], sc[256];
    s0[threadIdx.x] = c0; s1[threadIdx.x] = c1; s2[threadIdx.x] = c2; sc[threadIdx.x] = cnt;
    __syncthreads();
    for (int o = 128; o > 0; o >>= 1) {
        if (threadIdx.x < o) {
            s0[threadIdx.x] += s0[threadIdx.x + o];
            s1[threadIdx.x] += s1[threadIdx.x + o];
            s2[threadIdx.x] += s2[threadIdx.x + o];
            sc[threadIdx.x] += sc[threadIdx.x + o];
        }
        __syncthreads();
    }
    if (threadIdx.x == 0) {
        float* q = &g_part[(lab * 8 + slice) * 4];
        q[0] = s0[0]; q[1] = s1[0]; q[2] = s2[0]; q[3] = sc[0];
    }
}

__global__ void segfin_k() {
    int lab = threadIdx.x;
    if (lab >= NUM_INST) return;
    float s0 = 0.f, s1 = 0.f, s2 = 0.f, c = 0.f;
    for (int sl = 0; sl < 8; sl++) {
        const float* p = &g_part[(lab * 8 + sl) * 4];
        s0 += p[0]; s1 += p[1]; s2 += p[2]; c += p[3];
    }
    float d = fmaxf(c, 1.f);
    g_means[lab * 3 + 0] = s0 / d;
    g_means[lab * 3 + 1] = s1 / d;
    g_means[lab * 3 + 2] = s2 / d;
}

__global__ void gather_k(const int* __restrict__ inst, float* __restrict__ out) {
    int idx = blockIdx.x * 256 + threadIdx.x;
    const int Q = HH * WW / 4;
    if (idx >= BB * Q) return;
    int n = idx / Q, h4 = idx - n * Q;
    int4 lb = ((const int4*)inst)[(size_t)n * Q + h4];
#pragma unroll
    for (int c = 0; c < 3; c++) {
        float4 v;
        v.x = g_means[lb.x * 3 + c];
        v.y = g_means[lb.y * 3 + c];
        v.z = g_means[lb.z * 3 + c];
        v.w = g_means[lb.w * 3 + c];
        ((float4*)out)[(size_t)(n * 3 + c) * Q + h4] = v;
    }
}

// ---------------------------------------------------------------------------
extern "C" void kernel_launch(void* const* d_in, const int* in_sizes, int n_in,
                              void* d_out, int out_size) {
    const float* input = (const float*)d_in[0];
    const int* inst = (const int*)d_in[1];
    const float* w0 = (const float*)d_in[2];  const float* b0 = (const float*)d_in[3];
    const float* w1 = (const float*)d_in[4];  const float* b1 = (const float*)d_in[5];
    const float* w2 = (const float*)d_in[6];  const float* b2 = (const float*)d_in[7];
    const float* w3 = (const float*)d_in[8];  const float* b3 = (const float*)d_in[9];
    const float* w4 = (const float*)d_in[10]; const float* b4 = (const float*)d_in[11];
    const float* w5 = (const float*)d_in[12]; const float* b5 = (const float*)d_in[13];
    const float* w6 = (const float*)d_in[14]; const float* b6 = (const float*)d_in[15];
    const float* w7 = (const float*)d_in[16]; const float* b7 = (const float*)d_in[17];
    const float* w8 = (const float*)d_in[18]; const float* b8 = (const float*)d_in[19];
    const float* w9 = (const float*)d_in[20]; const float* b9 = (const float*)d_in[21];
    float* out = (float*)d_out;

    float* bufA;
    float* bufB;
    cudaGetSymbolAddress((void**)&bufA, g_bufA);
    cudaGetSymbolAddress((void**)&bufB, g_bufB);

    // conv0: [4,3,512,512] -> [4,16,512,512]
    conv7_first<<<dim3(128, BB), 256>>>(input, w0, b0, bufA);
    stats_k<<<BB * 16, 256>>>(bufA, 512 * 512);

    conv_s2_t<16, 32, 8, 4, 512, 512, true><<<dim3(16, BB * 4), 256>>>(bufA, w1, b1, bufB);
    stats_k<<<BB * 32, 256>>>(bufB, 256 * 256);

    conv_s2_t<32, 64, 8, 4, 256, 256, true><<<dim3(4, BB * 8), 256>>>(bufB, w2, b2, bufA);
    stats_k<<<BB * 64, 256>>>(bufA, 128 * 128);

    conv_s2_t<64, 128, 4, 4, 128, 128, true><<<dim3(1, BB * 32), 256>>>(bufA, w3, b3, bufB);
    stats_k<<<BB * 128, 256>>>(bufB, 64 * 64);

    conv_s2_t<128, 256, 8, 2, 64, 64, true><<<dim3(1, BB * 32), 256>>>(bufB, w4, b4, bufA);
    stats_k<<<BB * 256, 256>>>(bufA, 32 * 32);

    deconv_t<256, 128, 4, 4, 32, 32, true><<<dim3(1, BB * 32), 256>>>(bufA, w5, b5, bufB);
    stats_k<<<BB * 128, 256>>>(bufB, 64 * 64);

    deconv_t<128, 64, 8, 4, 64, 64, true><<<dim3(4, BB * 8), 256>>>(bufB, w6, b6, bufA);
    stats_k<<<BB * 64, 256>>>(bufA, 128 * 128);

    deconv_t<64, 32, 8, 4, 128, 128, true><<<dim3(16, BB * 4), 256>>>(bufA, w7, b7, bufB);
    stats_k<<<BB * 32, 256>>>(bufB, 256 * 256);

    deconv_t<32, 16, 8, 4, 256, 256, true><<<dim3(64, BB * 2), 256>>>(bufB, w8, b8, bufA);
    stats_k<<<BB * 16, 256>>>(bufA, 512 * 512);

    // conv9 + tanh: [4,16,512,512] -> [4,3,512,512]
    conv7_last<<<dim3(128, BB), 256>>>(bufA, w9, b9, bufB);

    // segment mean + gather
    segpart_k<<<dim3(NUM_INST, 8), 256>>>(bufB, inst);
    segfin_k<<<1, 32>>>();
    gather_k<<<(BB * HH * WW / 4 + 255) / 256, 256>>>(inst, out);
}

// round 7
// speedup vs baseline: 2.7595x; 1.0538x over previous
#include <cuda_runtime.h>
#include <math.h>

#define BB 4
#define HH 512
#define WW 512
#define NUM_INST 32
#define EPS 1e-5f
#define MAXB 128

// Ping-pong activation buffers (max 4*16*512*512 floats = 64MB each)
__device__ float g_bufA[BB * 16 * HH * WW];
__device__ float g_bufB[BB * 16 * HH * WW];
__device__ float g_stats[BB * 256 * 2];      // (mean, rstd) per (n,channel) plane
__device__ float2 g_ps[BB * 256 * MAXB];     // per-(plane,block) partial (sum, sumsq)
__device__ float g_means[NUM_INST * 3];
__device__ float g_part[NUM_INST * 8 * 4];

__device__ __forceinline__ int refl(int i, int n) {
    return i < 0 ? -i : (i >= n ? 2 * n - 2 - i : i);
}

// ---------------------------------------------------------------------------
// Finalize per-plane stats from block partials.
// ---------------------------------------------------------------------------
__global__ void statsfin_k(int nblk, float invHW) {
    int plane = blockIdx.x;
    float s = 0.f, q = 0.f;
    const float2* p = g_ps + (size_t)plane * MAXB;
    for (int i = threadIdx.x; i < nblk; i += 32) {
        float2 v = p[i];
        s += v.x;
        q += v.y;
    }
    for (int o = 16; o; o >>= 1) {
        s += __shfl_down_sync(0xffffffffu, s, o);
        q += __shfl_down_sync(0xffffffffu, q, o);
    }
    if (threadIdx.x == 0) {
        float m = s * invHW;
        float var = q * invHW - m * m;
        g_stats[plane * 2] = m;
        g_stats[plane * 2 + 1] = rsqrtf(var + EPS);
    }
}

// ---------------------------------------------------------------------------
// 3x3 stride-2 conv, zero pad 1, fused InstanceNorm+ReLU on INPUT, fused
// stats partial reduction on OUTPUT. Thread = TSxTS outputs x COPT channels.
// Weights staged in smem, read as float4.
// ---------------------------------------------------------------------------
template <int CIN, int COUT, int COPT, int TS, int HIN, int WIN, int NT, bool NORM>
__global__ void __launch_bounds__(NT) conv_s2_t(const float* __restrict__ x,
                                                const float* __restrict__ w,
                                                const float* __restrict__ bias,
                                                float* __restrict__ y) {
    constexpr int HOUT = HIN / 2, WOUT = WIN / 2;
    constexpr int TW = WOUT / TS;
    constexpr int CHUNK = (CIN < 64) ? CIN : 64;
    constexpr int NX = 2 * TS + 1;
    constexpr int V = COPT / 4;
    __shared__ __align__(16) float wsm[CHUNK * 9 * COPT];
    __shared__ float ssm[NT / 32][COPT], qsm[NT / 32][COPT];

    int t = blockIdx.x * NT + threadIdx.x;
    int cog = blockIdx.y % (COUT / COPT);
    int n = blockIdx.y / (COUT / COPT);
    int oh0 = (t / TW) * TS, ow0 = (t % TW) * TS;

    int iwv[NX]; bool cvl[NX];
#pragma unroll
    for (int c = 0; c < NX; c++) {
        int iw = ow0 * 2 - 1 + c;
        iwv[c] = iw;
        cvl[c] = (unsigned)iw < (unsigned)WIN;
    }

    float acc[TS * TS * COPT];
#pragma unroll
    for (int i = 0; i < TS * TS * COPT; i++) acc[i] = 0.f;

#pragma unroll 1
    for (int c0 = 0; c0 < CIN; c0 += CHUNK) {
        __syncthreads();
        for (int i = threadIdx.x; i < CHUNK * 9 * COPT; i += NT) {
            int ci_l = i / (9 * COPT);
            int rem = i - ci_l * (9 * COPT);
            int tap = rem / COPT;
            int u = rem - tap * COPT;
            wsm[i] = w[((size_t)(cog * COPT + u) * CIN + c0 + ci_l) * 9 + tap];
        }
        __syncthreads();
#pragma unroll 1
        for (int ci_l = 0; ci_l < CHUNK; ci_l++) {
            int ci = c0 + ci_l;
            const float* xp = x + (size_t)(n * CIN + ci) * HIN * WIN;
            float mn = 0.f, rs = 1.f;
            if (NORM) {
                mn = g_stats[(n * CIN + ci) * 2];
                rs = g_stats[(n * CIN + ci) * 2 + 1];
            }
#pragma unroll 1
            for (int r = 0; r < NX; r++) {
                int ih = oh0 * 2 - 1 + r;
                bool rv = (unsigned)ih < (unsigned)HIN;
                const float* xr = xp + (size_t)ih * WIN;
                float xv[NX];
#pragma unroll
                for (int c = 0; c < NX; c++) {
                    bool v = rv && cvl[c];
                    float raw = v ? xr[iwv[c]] : 0.f;
                    xv[c] = (NORM && v) ? fmaxf((raw - mn) * rs, 0.f) : raw;
                }
#pragma unroll
                for (int orow = 0; orow < TS; orow++) {
                    int kh = r - 2 * orow;
                    if (kh >= 0 && kh < 3) {
                        const float4* wp4 =
                            reinterpret_cast<const float4*>(wsm + (ci_l * 9 + kh * 3) * COPT);
#pragma unroll
                        for (int kw = 0; kw < 3; kw++) {
#pragma unroll
                            for (int v = 0; v < V; v++) {
                                float4 wq = wp4[kw * V + v];
                                float wa[4] = {wq.x, wq.y, wq.z, wq.w};
#pragma unroll
                                for (int j = 0; j < 4; j++) {
#pragma unroll
                                    for (int oc = 0; oc < TS; oc++)
                                        acc[(orow * TS + oc) * COPT + v * 4 + j] =
                                            fmaf(xv[2 * oc + kw], wa[j],
                                                 acc[(orow * TS + oc) * COPT + v * 4 + j]);
                                }
                            }
                        }
                    }
                }
            }
        }
    }
    // add bias
#pragma unroll
    for (int u = 0; u < COPT; u++) {
        float bv = bias[cog * COPT + u];
#pragma unroll
        for (int p = 0; p < TS * TS; p++) acc[p * COPT + u] += bv;
    }
    // stores
    size_t obase = (size_t)(n * COUT + cog * COPT) * HOUT * WOUT + (size_t)oh0 * WOUT + ow0;
#pragma unroll
    for (int u = 0; u < COPT; u++) {
#pragma unroll
        for (int orow = 0; orow < TS; orow++) {
            float* yp = y + obase + (size_t)u * HOUT * WOUT + (size_t)orow * WOUT;
            if (TS == 4) {
                float4 v;
                v.x = acc[(orow * TS + 0) * COPT + u];
                v.y = acc[(orow * TS + 1) * COPT + u];
                v.z = acc[(orow * TS + 2) * COPT + u];
                v.w = acc[(orow * TS + 3) * COPT + u];
                *reinterpret_cast<float4*>(yp) = v;
            } else {
                float2 v;
                v.x = acc[(orow * TS + 0) * COPT + u];
                v.y = acc[(orow * TS + 1) * COPT + u];
                *reinterpret_cast<float2*>(yp) = v;
            }
        }
    }
    // fused stats partial (deterministic)
    int lane = threadIdx.x & 31, wrp = threadIdx.x >> 5;
#pragma unroll
    for (int u = 0; u < COPT; u++) {
        float s = 0.f, q = 0.f;
#pragma unroll
        for (int p = 0; p < TS * TS; p++) {
            float v = acc[p * COPT + u];
            s += v;
            q += v * v;
        }
        for (int o = 16; o; o >>= 1) {
            s += __shfl_down_sync(0xffffffffu, s, o);
            q += __shfl_down_sync(0xffffffffu, q, o);
        }
        if (lane == 0) { ssm[wrp][u] = s; qsm[wrp][u] = q; }
    }
    __syncthreads();
    if (threadIdx.x < COPT) {
        float s = 0.f, q = 0.f;
#pragma unroll
        for (int wpp = 0; wpp < NT / 32; wpp++) { s += ssm[wpp][threadIdx.x]; q += qsm[wpp][threadIdx.x]; }
        int plane = n * COUT + cog * COPT + threadIdx.x;
        g_ps[(size_t)plane * MAXB + blockIdx.x] = make_float2(s, q);
    }
}

// ---------------------------------------------------------------------------
// ConvTranspose2d k=3 s=2 p=1 op=1, fused norm+relu on input, fused stats on
// output. Thread = TSxTS outputs x COPT channels. Weight layout (CIN,COUT,3,3).
// ---------------------------------------------------------------------------
template <int CIN, int COUT, int COPT, int TS, int HIN, int WIN, int NT, bool NORM>
__global__ void __launch_bounds__(NT) deconv_t(const float* __restrict__ x,
                                               const float* __restrict__ w,
                                               const float* __restrict__ bias,
                                               float* __restrict__ y) {
    constexpr int HOUT = HIN * 2, WOUT = WIN * 2;
    constexpr int TW = WOUT / TS;
    constexpr int SUB = TS / 2;
    constexpr int CHUNK = (CIN < 64) ? CIN : 64;
    constexpr int V = COPT / 4;
    __shared__ __align__(16) float wsm[CHUNK * 9 * COPT];
    __shared__ float ssm[NT / 32][COPT], qsm[NT / 32][COPT];

    int t = blockIdx.x * NT + threadIdx.x;
    int cog = blockIdx.y % (COUT / COPT);
    int n = blockIdx.y / (COUT / COPT);
    int oh0 = (t / TW) * TS, ow0 = (t % TW) * TS;
    int i0 = oh0 >> 1, j0 = ow0 >> 1;

    float acc[TS * TS * COPT];
#pragma unroll
    for (int i = 0; i < TS * TS * COPT; i++) acc[i] = 0.f;

#pragma unroll 1
    for (int c0 = 0; c0 < CIN; c0 += CHUNK) {
        __syncthreads();
        for (int i = threadIdx.x; i < CHUNK * 9 * COPT; i += NT) {
            int ci_l = i / (9 * COPT);
            int rem = i - ci_l * (9 * COPT);
            int tap = rem / COPT;
            int u = rem - tap * COPT;
            wsm[i] = w[((size_t)(c0 + ci_l) * COUT + cog * COPT + u) * 9 + tap];
        }
        __syncthreads();
#pragma unroll 1
        for (int ci_l = 0; ci_l < CHUNK; ci_l++) {
            int ci = c0 + ci_l;
            const float* xp = x + (size_t)(n * CIN + ci) * HIN * WIN;
            float mn = 0.f, rs = 1.f;
            if (NORM) {
                mn = g_stats[(n * CIN + ci) * 2];
                rs = g_stats[(n * CIN + ci) * 2 + 1];
            }
            float xr[(SUB + 1) * (SUB + 1)];
#pragma unroll
            for (int r = 0; r <= SUB; r++) {
                bool rv = (i0 + r) < HIN;
                const float* xpr = xp + (size_t)(i0 + r) * WIN;
#pragma unroll
                for (int c = 0; c <= SUB; c++) {
                    bool v = rv && (j0 + c) < WIN;
                    float raw = v ? xpr[j0 + c] : 0.f;
                    xr[r * (SUB + 1) + c] = (NORM && v) ? fmaxf((raw - mn) * rs, 0.f) : raw;
                }
            }
#pragma unroll
            for (int kh = 0; kh < 3; kh++) {
                int orl = (kh == 1) ? 0 : 1;
                int xro = (kh == 0) ? 1 : 0;
#pragma unroll
                for (int kw = 0; kw < 3; kw++) {
                    int ocl = (kw == 1) ? 0 : 1;
                    int xco = (kw == 0) ? 1 : 0;
                    const float4* wp4 =
                        reinterpret_cast<const float4*>(wsm + (ci_l * 9 + kh * 3 + kw) * COPT);
#pragma unroll
                    for (int v = 0; v < V; v++) {
                        float4 wq = wp4[v];
                        float wa[4] = {wq.x, wq.y, wq.z, wq.w};
#pragma unroll
                        for (int j = 0; j < 4; j++) {
#pragma unroll
                            for (int a = 0; a < SUB; a++)
#pragma unroll
                                for (int b = 0; b < SUB; b++)
                                    acc[((2 * a + orl) * TS + (2 * b + ocl)) * COPT + v * 4 + j] =
                                        fmaf(xr[(a + xro) * (SUB + 1) + (b + xco)], wa[j],
                                             acc[((2 * a + orl) * TS + (2 * b + ocl)) * COPT + v * 4 + j]);
                        }
                    }
                }
            }
        }
    }
#pragma unroll
    for (int u = 0; u < COPT; u++) {
        float bv = bias[cog * COPT + u];
#pragma unroll
        for (int p = 0; p < TS * TS; p++) acc[p * COPT + u] += bv;
    }
    size_t obase = (size_t)(n * COUT + cog * COPT) * HOUT * WOUT + (size_t)oh0 * WOUT + ow0;
#pragma unroll
    for (int u = 0; u < COPT; u++) {
#pragma unroll
        for (int orow = 0; orow < TS; orow++) {
            float* yp = y + obase + (size_t)u * HOUT * WOUT + (size_t)orow * WOUT;
            float4 v;
            v.x = acc[(orow * TS + 0) * COPT + u];
            v.y = acc[(orow * TS + 1) * COPT + u];
            v.z = acc[(orow * TS + 2) * COPT + u];
            v.w = acc[(orow * TS + 3) * COPT + u];
            *reinterpret_cast<float4*>(yp) = v;
        }
    }
    int lane = threadIdx.x & 31, wrp = threadIdx.x >> 5;
#pragma unroll
    for (int u = 0; u < COPT; u++) {
        float s = 0.f, q = 0.f;
#pragma unroll
        for (int p = 0; p < TS * TS; p++) {
            float v = acc[p * COPT + u];
            s += v;
            q += v * v;
        }
        for (int o = 16; o; o >>= 1) {
            s += __shfl_down_sync(0xffffffffu, s, o);
            q += __shfl_down_sync(0xffffffffu, q, o);
        }
        if (lane == 0) { ssm[wrp][u] = s; qsm[wrp][u] = q; }
    }
    __syncthreads();
    if (threadIdx.x < COPT) {
        float s = 0.f, q = 0.f;
#pragma unroll
        for (int wpp = 0; wpp < NT / 32; wpp++) { s += ssm[wpp][threadIdx.x]; q += qsm[wpp][threadIdx.x]; }
        int plane = n * COUT + cog * COPT + threadIdx.x;
        g_ps[(size_t)plane * MAXB + blockIdx.x] = make_float2(s, q);
    }
}

// ---------------------------------------------------------------------------
// conv0: reflect-pad 3, 7x7, 3->16. Thread = 1 row x 8 cols, all 16 co.
// Fused stats partials on output.
// ---------------------------------------------------------------------------
__global__ void __launch_bounds__(256) conv7_first(const float* __restrict__ x,
                                                   const float* __restrict__ w,
                                                   const float* __restrict__ bias,
                                                   float* __restrict__ y) {
    __shared__ __align__(16) float wsm[3 * 49 * 16];
    __shared__ float ssm[8][16], qsm[8][16];
    for (int i = threadIdx.x; i < 3 * 49 * 16; i += 256) {
        int ci = i / (49 * 16);
        int rem = i - ci * (49 * 16);
        int tap = rem / 16;
        int co = rem - tap * 16;
        wsm[i] = w[(co * 3 + ci) * 49 + tap];
    }
    __syncthreads();

    int t = blockIdx.x * 256 + threadIdx.x;
    int n = blockIdx.y;
    int oh = t >> 6;
    int ow0 = (t & 63) * 8;

    int iwI[14];
#pragma unroll
    for (int c = 0; c < 14; c++) iwI[c] = refl(ow0 - 3 + c, WW);

    float acc[8 * 16];
#pragma unroll
    for (int i = 0; i < 8 * 16; i++) acc[i] = 0.f;

#pragma unroll 1
    for (int ci = 0; ci < 3; ci++) {
        const float* xp = x + (size_t)(n * 3 + ci) * HH * WW;
#pragma unroll 1
        for (int kh = 0; kh < 7; kh++) {
            const float* xr = xp + (size_t)refl(oh + kh - 3, HH) * WW;
            float xv[14];
#pragma unroll
            for (int c = 0; c < 14; c++) xv[c] = xr[iwI[c]];
            const float4* wb4 = reinterpret_cast<const float4*>(wsm + (ci * 49 + kh * 7) * 16);
#pragma unroll
            for (int kw = 0; kw < 7; kw++) {
#pragma unroll
                for (int v = 0; v < 4; v++) {
                    float4 wq = wb4[kw * 4 + v];
                    float wa[4] = {wq.x, wq.y, wq.z, wq.w};
#pragma unroll
                    for (int j = 0; j < 4; j++) {
#pragma unroll
                        for (int sc = 0; sc < 8; sc++)
                            acc[sc * 16 + v * 4 + j] = fmaf(xv[sc + kw], wa[j], acc[sc * 16 + v * 4 + j]);
                    }
                }
            }
        }
    }
#pragma unroll
    for (int co = 0; co < 16; co++) {
        float bv = bias[co];
#pragma unroll
        for (int sc = 0; sc < 8; sc++) acc[sc * 16 + co] += bv;
    }
#pragma unroll
    for (int co = 0; co < 16; co++) {
        float* yp = y + (size_t)(n * 16 + co) * HH * WW + (size_t)oh * WW + ow0;
        float4 v0, v1;
        v0.x = acc[0 * 16 + co]; v0.y = acc[1 * 16 + co];
        v0.z = acc[2 * 16 + co]; v0.w = acc[3 * 16 + co];
        v1.x = acc[4 * 16 + co]; v1.y = acc[5 * 16 + co];
        v1.z = acc[6 * 16 + co]; v1.w = acc[7 * 16 + co];
        ((float4*)yp)[0] = v0;
        ((float4*)yp)[1] = v1;
    }
    int lane = threadIdx.x & 31, wrp = threadIdx.x >> 5;
#pragma unroll
    for (int co = 0; co < 16; co++) {
        float s = 0.f, q = 0.f;
#pragma unroll
        for (int sc = 0; sc < 8; sc++) {
            float v = acc[sc * 16 + co];
            s += v;
            q += v * v;
        }
        for (int o = 16; o; o >>= 1) {
            s += __shfl_down_sync(0xffffffffu, s, o);
            q += __shfl_down_sync(0xffffffffu, q, o);
        }
        if (lane == 0) { ssm[wrp][co] = s; qsm[wrp][co] = q; }
    }
    __syncthreads();
    if (threadIdx.x < 16) {
        float s = 0.f, q = 0.f;
#pragma unroll
        for (int wpp = 0; wpp < 8; wpp++) { s += ssm[wpp][threadIdx.x]; q += qsm[wpp][threadIdx.x]; }
        int plane = n * 16 + threadIdx.x;
        g_ps[(size_t)plane * MAXB + blockIdx.x] = make_float2(s, q);
    }
}

// ---------------------------------------------------------------------------
// conv9: reflect-pad 3, 7x7, 16->3, norm+relu on input, tanh on output.
// ---------------------------------------------------------------------------
__global__ void __launch_bounds__(256) conv7_last(const float* __restrict__ x,
                                                  const float* __restrict__ w,
                                                  const float* __restrict__ bias,
                                                  float* __restrict__ y) {
    __shared__ float wsm[16 * 49 * 3];
    for (int i = threadIdx.x; i < 16 * 49 * 3; i += 256) {
        int ci = i / (49 * 3);
        int rem = i - ci * (49 * 3);
        int tap = rem / 3;
        int co = rem - tap * 3;
        wsm[i] = w[(co * 16 + ci) * 49 + tap];
    }
    __syncthreads();

    int t = blockIdx.x * 256 + threadIdx.x;
    int n = blockIdx.y;
    int oh = t >> 6;
    int ow0 = (t & 63) * 8;

    int iwI[14];
#pragma unroll
    for (int c = 0; c < 14; c++) iwI[c] = refl(ow0 - 3 + c, WW);

    float acc[8 * 3];
#pragma unroll
    for (int i = 0; i < 8 * 3; i++) acc[i] = 0.f;

#pragma unroll 1
    for (int ci = 0; ci < 16; ci++) {
        const float* xp = x + (size_t)(n * 16 + ci) * HH * WW;
        float mn = g_stats[(n * 16 + ci) * 2];
        float rs = g_stats[(n * 16 + ci) * 2 + 1];
#pragma unroll 1
        for (int kh = 0; kh < 7; kh++) {
            const float* xr = xp + (size_t)refl(oh + kh - 3, HH) * WW;
            float xv[14];
#pragma unroll
            for (int c = 0; c < 14; c++) xv[c] = fmaxf((xr[iwI[c]] - mn) * rs, 0.f);
            const float* wb = wsm + (ci * 49 + kh * 7) * 3;
#pragma unroll
            for (int kw = 0; kw < 7; kw++) {
#pragma unroll
                for (int co = 0; co < 3; co++) {
                    float wvv = wb[kw * 3 + co];
#pragma unroll
                    for (int sc = 0; sc < 8; sc++)
                        acc[sc * 3 + co] = fmaf(xv[sc + kw], wvv, acc[sc * 3 + co]);
                }
            }
        }
    }
#pragma unroll
    for (int co = 0; co < 3; co++) {
        float bv = bias[co];
        float* yp = y + (size_t)(n * 3 + co) * HH * WW + (size_t)oh * WW + ow0;
        float4 v0, v1;
        v0.x = tanhf(acc[0 * 3 + co] + bv); v0.y = tanhf(acc[1 * 3 + co] + bv);
        v0.z = tanhf(acc[2 * 3 + co] + bv); v0.w = tanhf(acc[3 * 3 + co] + bv);
        v1.x = tanhf(acc[4 * 3 + co] + bv); v1.y = tanhf(acc[5 * 3 + co] + bv);
        v1.z = tanhf(acc[6 * 3 + co] + bv); v1.w = tanhf(acc[7 * 3 + co] + bv);
        ((float4*)yp)[0] = v0;
        ((float4*)yp)[1] = v1;
    }
}

// ---------------------------------------------------------------------------
// Segment mean: (label, slice) partials, deterministic, then combine.
// ---------------------------------------------------------------------------
__global__ void segpart_k(const float* __restrict__ feats, const int* __restrict__ inst) {
    int lab = blockIdx.x, slice = blockIdx.y;
    const int HWp = HH * WW;
    const int per = BB * HWp / 8;
    int start = slice * per;
    float c0 = 0.f, c1 = 0.f, c2 = 0.f, cnt = 0.f;
    for (int p = start + threadIdx.x; p < start + per; p += 256) {
        if (inst[p] == lab) {
            int n = p / HWp;
            int hw = p - n * HWp;
            const float* f = feats + (size_t)n * 3 * HWp + hw;
            c0 += f[0];
            c1 += f[HWp];
            c2 += f[2 * HWp];
            cnt += 1.f;
        }
    }
    __shared__ float s0[256], s1[256], s2[256], sc[256];
    s0[threadIdx.x] = c0; s1[threadIdx.x] = c1; s2[threadIdx.x] = c2; sc[threadIdx.x] = cnt;
    __syncthreads();
    for (int o = 128; o > 0; o >>= 1) {
        if (threadIdx.x < o) {
            s0[threadIdx.x] += s0[threadIdx.x + o];
            s1[threadIdx.x] += s1[threadIdx.x + o];
            s2[threadIdx.x] += s2[threadIdx.x + o];
            sc[threadIdx.x] += sc[threadIdx.x + o];
        }
        __syncthreads();
    }
    if (threadIdx.x == 0) {
        float* q = &g_part[(lab * 8 + slice) * 4];
        q[0] = s0[0]; q[1] = s1[0]; q[2] = s2[0]; q[3] = sc[0];
    }
}

__global__ void segfin_k() {
    int lab = threadIdx.x;
    if (lab >= NUM_INST) return;
    float s0 = 0.f, s1 = 0.f, s2 = 0.f, c = 0.f;
    for (int sl = 0; sl < 8; sl++) {
        const float* p = &g_part[(lab * 8 + sl) * 4];
        s0 += p[0]; s1 += p[1]; s2 += p[2]; c += p[3];
    }
    float d = fmaxf(c, 1.f);
    g_means[lab * 3 + 0] = s0 / d;
    g_means[lab * 3 + 1] = s1 / d;
    g_means[lab * 3 + 2] = s2 / d;
}

__global__ void gather_k(const int* __restrict__ inst, float* __restrict__ out) {
    int idx = blockIdx.x * 256 + threadIdx.x;
    const int Q = HH * WW / 4;
    if (idx >= BB * Q) return;
    int n = idx / Q, h4 = idx - n * Q;
    int4 lb = ((const int4*)inst)[(size_t)n * Q + h4];
#pragma unroll
    for (int c = 0; c < 3; c++) {
        float4 v;
        v.x = g_means[lb.x * 3 + c];
        v.y = g_means[lb.y * 3 + c];
        v.z = g_means[lb.z * 3 + c];
        v.w = g_means[lb.w * 3 + c];
        ((float4*)out)[(size_t)(n * 3 + c) * Q + h4] = v;
    }
}

// ---------------------------------------------------------------------------
extern "C" void kernel_launch(void* const* d_in, const int* in_sizes, int n_in,
                              void* d_out, int out_size) {
    const float* input = (const float*)d_in[0];
    const int* inst = (const int*)d_in[1];
    const float* w0 = (const float*)d_in[2];  const float* b0 = (const float*)d_in[3];
    const float* w1 = (const float*)d_in[4];  const float* b1 = (const float*)d_in[5];
    const float* w2 = (const float*)d_in[6];  const float* b2 = (const float*)d_in[7];
    const float* w3 = (const float*)d_in[8];  const float* b3 = (const float*)d_in[9];
    const float* w4 = (const float*)d_in[10]; const float* b4 = (const float*)d_in[11];
    const float* w5 = (const float*)d_in[12]; const float* b5 = (const float*)d_in[13];
    const float* w6 = (const float*)d_in[14]; const float* b6 = (const float*)d_in[15];
    const float* w7 = (const float*)d_in[16]; const float* b7 = (const float*)d_in[17];
    const float* w8 = (const float*)d_in[18]; const float* b8 = (const float*)d_in[19];
    const float* w9 = (const float*)d_in[20]; const float* b9 = (const float*)d_in[21];
    float* out = (float*)d_out;

    float* bufA;
    float* bufB;
    cudaGetSymbolAddress((void**)&bufA, g_bufA);
    cudaGetSymbolAddress((void**)&bufB, g_bufB);

    // conv0: [4,3,512,512] -> [4,16,512,512]
    conv7_first<<<dim3(128, BB), 256>>>(input, w0, b0, bufA);
    statsfin_k<<<BB * 16, 32>>>(128, 1.f / (512.f * 512.f));

    conv_s2_t<16, 32, 8, 4, 512, 512, 256, true><<<dim3(16, BB * 4), 256>>>(bufA, w1, b1, bufB);
    statsfin_k<<<BB * 32, 32>>>(16, 1.f / (256.f * 256.f));

    conv_s2_t<32, 64, 8, 4, 256, 256, 128, true><<<dim3(8, BB * 8), 128>>>(bufB, w2, b2, bufA);
    statsfin_k<<<BB * 64, 32>>>(8, 1.f / (128.f * 128.f));

    conv_s2_t<64, 128, 4, 4, 128, 128, 128, true><<<dim3(2, BB * 32), 128>>>(bufA, w3, b3, bufB);
    statsfin_k<<<BB * 128, 32>>>(2, 1.f / (64.f * 64.f));

    conv_s2_t<128, 256, 8, 2, 64, 64, 128, true><<<dim3(2, BB * 32), 128>>>(bufB, w4, b4, bufA);
    statsfin_k<<<BB * 256, 32>>>(2, 1.f / (32.f * 32.f));

    deconv_t<256, 128, 4, 4, 32, 32, 128, true><<<dim3(2, BB * 32), 128>>>(bufA, w5, b5, bufB);
    statsfin_k<<<BB * 128, 32>>>(2, 1.f / (64.f * 64.f));

    deconv_t<128, 64, 8, 4, 64, 64, 128, true><<<dim3(8, BB * 8), 128>>>(bufB, w6, b6, bufA);
    statsfin_k<<<BB * 64, 32>>>(8, 1.f / (128.f * 128.f));

    deconv_t<64, 32, 8, 4, 128, 128, 256, true><<<dim3(16, BB * 4), 256>>>(bufA, w7, b7, bufB);
    statsfin_k<<<BB * 32, 32>>>(16, 1.f / (256.f * 256.f));

    deconv_t<32, 16, 8, 4, 256, 256, 256, true><<<dim3(64, BB * 2), 256>>>(bufB, w8, b8, bufA);
    statsfin_k<<<BB * 16, 32>>>(64, 1.f / (512.f * 512.f));

    // conv9 + tanh: [4,16,512,512] -> [4,3,512,512]
    conv7_last<<<dim3(128, BB), 256>>>(bufA, w9, b9, bufB);

    // segment mean + gather
    segpart_k<<<dim3(NUM_INST, 8), 256>>>(bufB, inst);
    segfin_k<<<1, 32>>>();
    gather_k<<<(BB * HH * WW / 4 + 255) / 256, 256>>>(inst, out);
}